// round 1
// baseline (speedup 1.0000x reference)
#include <cuda_runtime.h>
#include <cuda_bf16.h>
#include <math.h>

// ---------------------------------------------------------------------------
// TransformerBlock: B=8, S=1024, D=1024, H=16, DH=64, F=4096  (fp32)
//
// Pipeline:
//   1. Q = (x@Wq^T + bq)/8  -> (b,h,s,dh)      [gemm EPI_HEADS, scale=0.125]
//   2. K, V likewise (scale=1)
//   3. flash attention per (b,h,qtile) -> ctx (b,s,d)
//   4. sa = ctx@Wo^T + bo + x                  [gemm EPI_RES]
//   5. h  = LN1(sa)
//   6. ff = gelu(h@W1^T + b1)                  [gemm EPI_GELU]
//   7. f2 = ff@W2^T + b2 + h                   [gemm EPI_RES]
//   8. out = LN2(f2)
// ---------------------------------------------------------------------------

#define Bb 8
#define Ss 1024
#define Dd 1024
#define Hh 16
#define DH 64
#define Ff 4096
#define TT (Bb*Ss)          // 8192 tokens

// ------------------------- static device scratch ---------------------------
__device__ float g_q  [Bb*Hh*Ss*DH];   // 32 MB, (b,h,s,dh)
__device__ float g_k  [Bb*Hh*Ss*DH];
__device__ float g_v  [Bb*Hh*Ss*DH];
__device__ float g_ctx[TT*Dd];         // (t, d)
__device__ float g_sa [TT*Dd];
__device__ float g_h  [TT*Dd];
__device__ float g_ff [TT*Ff];         // 134 MB
__device__ float g_f2 [TT*Dd];

// ------------------------------ GEMM ---------------------------------------
// C[m,n] = sum_k A[m,k] * W[n,k]  (+ epilogue).  M=8192 fixed, N,K runtime.
// BM=BN=128, BK=8, 256 threads, 8x8 microtile.

#define EPI_HEADS 0
#define EPI_RES   1
#define EPI_GELU  2

__device__ __forceinline__ float gelu_exact(float v) {
    return 0.5f * v * (1.0f + erff(v * 0.70710678118654752440f));
}

template<int EPI>
__global__ void __launch_bounds__(256) gemm_k(
    const float* __restrict__ A, const float* __restrict__ W,
    const float* __restrict__ bias, const float* __restrict__ res,
    float* __restrict__ C, int N, int K, float scale)
{
    __shared__ float As[8][128];
    __shared__ float Bs[8][128];

    const int tid = threadIdx.x;
    const int m0 = blockIdx.y * 128;
    const int n0 = blockIdx.x * 128;

    const int lr = tid >> 1;           // 0..127
    const int lc = (tid & 1) << 2;     // 0 or 4
    const float* Ap = A + (size_t)(m0 + lr) * K + lc;
    const float* Wp = W + (size_t)(n0 + lr) * K + lc;

    const int tx = tid & 15;           // col group
    const int ty = tid >> 4;           // row group

    float acc[8][8];
#pragma unroll
    for (int i = 0; i < 8; i++)
#pragma unroll
        for (int j = 0; j < 8; j++) acc[i][j] = 0.f;

    for (int k0 = 0; k0 < K; k0 += 8) {
        float4 a4 = *(const float4*)(Ap + k0);
        float4 b4 = *(const float4*)(Wp + k0);
        __syncthreads();
        As[lc+0][lr] = a4.x; As[lc+1][lr] = a4.y;
        As[lc+2][lr] = a4.z; As[lc+3][lr] = a4.w;
        Bs[lc+0][lr] = b4.x; Bs[lc+1][lr] = b4.y;
        Bs[lc+2][lr] = b4.z; Bs[lc+3][lr] = b4.w;
        __syncthreads();
#pragma unroll
        for (int kk = 0; kk < 8; kk++) {
            float af[8], bf[8];
            *(float4*)(af    ) = *(const float4*)&As[kk][ty*8    ];
            *(float4*)(af + 4) = *(const float4*)&As[kk][ty*8 + 4];
            *(float4*)(bf    ) = *(const float4*)&Bs[kk][tx*8    ];
            *(float4*)(bf + 4) = *(const float4*)&Bs[kk][tx*8 + 4];
#pragma unroll
            for (int i = 0; i < 8; i++)
#pragma unroll
                for (int j = 0; j < 8; j++)
                    acc[i][j] = fmaf(af[i], bf[j], acc[i][j]);
        }
    }

#pragma unroll
    for (int i = 0; i < 8; i++) {
        const int m = m0 + ty*8 + i;
#pragma unroll
        for (int jj = 0; jj < 8; jj += 4) {
            const int n = n0 + tx*8 + jj;
            float4 r4;
            r4.x = acc[i][jj+0] + bias[n+0];
            r4.y = acc[i][jj+1] + bias[n+1];
            r4.z = acc[i][jj+2] + bias[n+2];
            r4.w = acc[i][jj+3] + bias[n+3];
            if (EPI == EPI_HEADS) {
                r4.x *= scale; r4.y *= scale; r4.z *= scale; r4.w *= scale;
                const int bb = m >> 10, s = m & 1023;
                const int hh = n >> 6, dh = n & 63;
                *(float4*)&C[(((size_t)bb*Hh + hh)*Ss + s)*DH + dh] = r4;
            } else if (EPI == EPI_RES) {
                const float4 rr = *(const float4*)&res[(size_t)m*N + n];
                r4.x += rr.x; r4.y += rr.y; r4.z += rr.z; r4.w += rr.w;
                *(float4*)&C[(size_t)m*N + n] = r4;
            } else { // EPI_GELU
                r4.x = gelu_exact(r4.x); r4.y = gelu_exact(r4.y);
                r4.z = gelu_exact(r4.z); r4.w = gelu_exact(r4.w);
                *(float4*)&C[(size_t)m*N + n] = r4;
            }
        }
    }
}

// --------------------------- flash attention --------------------------------
// One block per (qtile=64, h, b). 256 threads: thread = (row r=tid/4, group
// g=tid%4 owning 16 score-cols and 16 out-dims). Online softmax over 16
// kv-tiles of 64. All smem reads are broadcast or fully coalesced.

#define ATTN_SMEM_FLOATS (64*65 + 64*68 + 64*64 + 64*65 + 64)
#define ATTN_SMEM_BYTES  (ATTN_SMEM_FLOATS * 4)

__global__ void __launch_bounds__(256) attn_k(
    const float* __restrict__ Q, const float* __restrict__ Kg,
    const float* __restrict__ Vg, const int* __restrict__ mask,
    float* __restrict__ O)
{
    extern __shared__ float sm[];
    float* qs = sm;                 // [64][65]
    float* ks = qs + 64*65;         // [64][68]  d-major (transposed)
    float* vs = ks + 64*68;         // [64][64]
    float* ps = vs + 64*64;         // [64][65]
    float* mk = ps + 64*65;         // [64]

    const int tid = threadIdx.x;
    const int b = blockIdx.z, h = blockIdx.y, q0 = blockIdx.x * 64;

    const float* Qbh = Q + ((size_t)(b*Hh + h)*Ss + q0) * DH;
    const float* Kbh = Kg + (size_t)(b*Hh + h)*Ss*DH;
    const float* Vbh = Vg + (size_t)(b*Hh + h)*Ss*DH;

    for (int i = tid; i < 64*64; i += 256) {
        int r = i >> 6, d = i & 63;
        qs[r*65 + d] = Qbh[i];
    }

    const int r  = tid >> 2;
    const int g4 = tid & 3;
    const int c0 = g4 * 16;

    float out[16];
#pragma unroll
    for (int j = 0; j < 16; j++) out[j] = 0.f;
    float mrow = -INFINITY, l = 0.f;

    for (int kv0 = 0; kv0 < Ss; kv0 += 64) {
        __syncthreads();
        for (int i = tid; i < 64*64; i += 256) {
            int c = i >> 6, d = i & 63;
            ks[d*68 + c] = Kbh[kv0*DH + i];
        }
        for (int i = tid; i < 64*64; i += 256)
            vs[i] = Vbh[kv0*DH + i];
        if (tid < 64) mk[tid] = (float)mask[b*Ss + kv0 + tid];
        __syncthreads();

        float s[16];
#pragma unroll
        for (int j = 0; j < 16; j++) s[j] = 0.f;
        for (int d = 0; d < 64; d++) {
            const float qv = qs[r*65 + d];
            const float4* kr = (const float4*)&ks[d*68 + c0];
            float4 k0 = kr[0], k1 = kr[1], k2 = kr[2], k3 = kr[3];
            s[ 0] = fmaf(qv, k0.x, s[ 0]); s[ 1] = fmaf(qv, k0.y, s[ 1]);
            s[ 2] = fmaf(qv, k0.z, s[ 2]); s[ 3] = fmaf(qv, k0.w, s[ 3]);
            s[ 4] = fmaf(qv, k1.x, s[ 4]); s[ 5] = fmaf(qv, k1.y, s[ 5]);
            s[ 6] = fmaf(qv, k1.z, s[ 6]); s[ 7] = fmaf(qv, k1.w, s[ 7]);
            s[ 8] = fmaf(qv, k2.x, s[ 8]); s[ 9] = fmaf(qv, k2.y, s[ 9]);
            s[10] = fmaf(qv, k2.z, s[10]); s[11] = fmaf(qv, k2.w, s[11]);
            s[12] = fmaf(qv, k3.x, s[12]); s[13] = fmaf(qv, k3.y, s[13]);
            s[14] = fmaf(qv, k3.z, s[14]); s[15] = fmaf(qv, k3.w, s[15]);
        }

        float mloc = -INFINITY;
#pragma unroll
        for (int j = 0; j < 16; j++) {
            if (mk[c0 + j] == 0.f) s[j] = -1e30f;
            mloc = fmaxf(mloc, s[j]);
        }
        mloc = fmaxf(mloc, __shfl_xor_sync(0xffffffffu, mloc, 1));
        mloc = fmaxf(mloc, __shfl_xor_sync(0xffffffffu, mloc, 2));
        const float mnew = fmaxf(mrow, mloc);
        const float alpha = __expf(mrow - mnew);
        float lloc = 0.f;
#pragma unroll
        for (int j = 0; j < 16; j++) {
            s[j] = __expf(s[j] - mnew);
            lloc += s[j];
        }
        lloc += __shfl_xor_sync(0xffffffffu, lloc, 1);
        lloc += __shfl_xor_sync(0xffffffffu, lloc, 2);
        l = l * alpha + lloc;
#pragma unroll
        for (int j = 0; j < 16; j++) out[j] *= alpha;
#pragma unroll
        for (int j = 0; j < 16; j++) ps[r*65 + c0 + j] = s[j];
        __syncthreads();

        for (int c = 0; c < 64; c++) {
            const float pv = ps[r*65 + c];
            const float4* vr = (const float4*)&vs[c*64 + c0];
            float4 v0 = vr[0], v1 = vr[1], v2 = vr[2], v3 = vr[3];
            out[ 0] = fmaf(pv, v0.x, out[ 0]); out[ 1] = fmaf(pv, v0.y, out[ 1]);
            out[ 2] = fmaf(pv, v0.z, out[ 2]); out[ 3] = fmaf(pv, v0.w, out[ 3]);
            out[ 4] = fmaf(pv, v1.x, out[ 4]); out[ 5] = fmaf(pv, v1.y, out[ 5]);
            out[ 6] = fmaf(pv, v1.z, out[ 6]); out[ 7] = fmaf(pv, v1.w, out[ 7]);
            out[ 8] = fmaf(pv, v2.x, out[ 8]); out[ 9] = fmaf(pv, v2.y, out[ 9]);
            out[10] = fmaf(pv, v2.z, out[10]); out[11] = fmaf(pv, v2.w, out[11]);
            out[12] = fmaf(pv, v3.x, out[12]); out[13] = fmaf(pv, v3.y, out[13]);
            out[14] = fmaf(pv, v3.z, out[14]); out[15] = fmaf(pv, v3.w, out[15]);
        }
        mrow = mnew;
    }

    const float inv = 1.f / l;
    float* Orow = O + ((size_t)(b*Ss) + q0 + r) * Dd + h*DH + c0;
#pragma unroll
    for (int jj = 0; jj < 16; jj += 4) {
        float4 o4;
        o4.x = out[jj+0]*inv; o4.y = out[jj+1]*inv;
        o4.z = out[jj+2]*inv; o4.w = out[jj+3]*inv;
        *(float4*)&Orow[jj] = o4;
    }
}

// ------------------------------ LayerNorm -----------------------------------
__global__ void __launch_bounds__(256) ln_k(
    const float* __restrict__ X, const float* __restrict__ gg,
    const float* __restrict__ bb, float* __restrict__ Y)
{
    __shared__ float red[16];
    const int row = blockIdx.x, tid = threadIdx.x;
    const float4 x = ((const float4*)(X + (size_t)row * Dd))[tid];
    float s  = x.x + x.y + x.z + x.w;
    float s2 = x.x*x.x + x.y*x.y + x.z*x.z + x.w*x.w;
#pragma unroll
    for (int o = 16; o; o >>= 1) {
        s  += __shfl_xor_sync(0xffffffffu, s,  o);
        s2 += __shfl_xor_sync(0xffffffffu, s2, o);
    }
    const int w = tid >> 5, lane = tid & 31;
    if (lane == 0) { red[w] = s; red[8 + w] = s2; }
    __syncthreads();
    if (tid < 32) {
        float a = (tid < 8) ? red[tid]     : 0.f;
        float c = (tid < 8) ? red[8 + tid] : 0.f;
#pragma unroll
        for (int o = 4; o; o >>= 1) {
            a += __shfl_xor_sync(0xffffffffu, a, o);
            c += __shfl_xor_sync(0xffffffffu, c, o);
        }
        if (tid == 0) { red[0] = a; red[8] = c; }
    }
    __syncthreads();
    const float mean = red[0] * (1.f / Dd);
    const float var  = red[8] * (1.f / Dd) - mean * mean;
    const float rstd = rsqrtf(var + 1e-12f);
    const float4 gv = ((const float4*)gg)[tid];
    const float4 bv = ((const float4*)bb)[tid];
    float4 y;
    y.x = (x.x - mean) * rstd * gv.x + bv.x;
    y.y = (x.y - mean) * rstd * gv.y + bv.y;
    y.z = (x.z - mean) * rstd * gv.z + bv.z;
    y.w = (x.w - mean) * rstd * gv.w + bv.w;
    ((float4*)(Y + (size_t)row * Dd))[tid] = y;
}

// ------------------------------ launch --------------------------------------
extern "C" void kernel_launch(void* const* d_in, const int* in_sizes, int n_in,
                              void* d_out, int out_size)
{
    const float* x    = (const float*)d_in[0];
    const int*   amsk = (const int*)  d_in[1];
    const float* Wq   = (const float*)d_in[2];
    const float* bq   = (const float*)d_in[3];
    const float* Wk   = (const float*)d_in[4];
    const float* bk   = (const float*)d_in[5];
    const float* Wv   = (const float*)d_in[6];
    const float* bv   = (const float*)d_in[7];
    const float* Wo   = (const float*)d_in[8];
    const float* bo   = (const float*)d_in[9];
    const float* ln1g = (const float*)d_in[10];
    const float* ln1b = (const float*)d_in[11];
    const float* W1   = (const float*)d_in[12];
    const float* b1   = (const float*)d_in[13];
    const float* W2   = (const float*)d_in[14];
    const float* b2   = (const float*)d_in[15];
    const float* ln2g = (const float*)d_in[16];
    const float* ln2b = (const float*)d_in[17];
    float* out = (float*)d_out;

    float *qp, *kp, *vp, *ctxp, *sap, *hp, *ffp, *f2p;
    cudaGetSymbolAddress((void**)&qp,   g_q);
    cudaGetSymbolAddress((void**)&kp,   g_k);
    cudaGetSymbolAddress((void**)&vp,   g_v);
    cudaGetSymbolAddress((void**)&ctxp, g_ctx);
    cudaGetSymbolAddress((void**)&sap,  g_sa);
    cudaGetSymbolAddress((void**)&hp,   g_h);
    cudaGetSymbolAddress((void**)&ffp,  g_ff);
    cudaGetSymbolAddress((void**)&f2p,  g_f2);

    cudaFuncSetAttribute(attn_k, cudaFuncAttributeMaxDynamicSharedMemorySize,
                         ATTN_SMEM_BYTES);

    dim3 gD(Dd/128, TT/128);    // (8, 64)
    dim3 gF(Ff/128, TT/128);    // (32, 64)

    // 1-3. QKV projections (q scaled by 1/sqrt(DH)=0.125)
    gemm_k<EPI_HEADS><<<gD, 256>>>(x, Wq, bq, nullptr, qp, Dd, Dd, 0.125f);
    gemm_k<EPI_HEADS><<<gD, 256>>>(x, Wk, bk, nullptr, kp, Dd, Dd, 1.0f);
    gemm_k<EPI_HEADS><<<gD, 256>>>(x, Wv, bv, nullptr, vp, Dd, Dd, 1.0f);

    // 4. attention
    attn_k<<<dim3(Ss/64, Hh, Bb), 256, ATTN_SMEM_BYTES>>>(qp, kp, vp, amsk, ctxp);

    // 5. output projection + residual
    gemm_k<EPI_RES><<<gD, 256>>>(ctxp, Wo, bo, x, sap, Dd, Dd, 1.0f);

    // 6. LN1
    ln_k<<<TT, 256>>>(sap, ln1g, ln1b, hp);

    // 7. FFN up + gelu
    gemm_k<EPI_GELU><<<gF, 256>>>(hp, W1, b1, nullptr, ffp, Ff, Dd, 1.0f);

    // 8. FFN down + residual
    gemm_k<EPI_RES><<<gD, 256>>>(ffp, W2, b2, hp, f2p, Dd, Ff, 1.0f);

    // 9. LN2 -> output
    ln_k<<<TT, 256>>>(f2p, ln2g, ln2b, out);
}

// round 3
// speedup vs baseline: 4.8642x; 4.8642x over previous
#include <cuda_runtime.h>
#include <cuda_bf16.h>
#include <math.h>
#include <stdint.h>

// ---------------------------------------------------------------------------
// TransformerBlock B=8 S=1024 D=1024 H=16 DH=64 F=4096 (fp32 in/out)
// All matmuls on mma.sync.m16n8k16 bf16 (x3 hi/lo split, fp32 accum).
// ---------------------------------------------------------------------------

#define Bb 8
#define Ss 1024
#define Dd 1024
#define Hh 16
#define DH 64
#define Ff 4096
#define TT (Bb*Ss)

typedef __nv_bfloat16 bf16;

// ------------------------- static device scratch ---------------------------
__device__ float g_sa[TT*Dd];
__device__ float g_h [TT*Dd];
__device__ float g_f2[TT*Dd];
__device__ float g_mf[Bb*Ss];

__device__ bf16 g_xh [TT*Dd],  g_xl [TT*Dd];
__device__ bf16 g_qh [TT*Dd],  g_ql [TT*Dd];
__device__ bf16 g_kh [TT*Dd],  g_kl [TT*Dd];
__device__ bf16 g_vh [TT*Dd],  g_vl [TT*Dd];
__device__ bf16 g_cxh[TT*Dd],  g_cxl[TT*Dd];
__device__ bf16 g_hh [TT*Dd],  g_hl [TT*Dd];
__device__ bf16 g_fh [TT*Ff],  g_fl [TT*Ff];
__device__ bf16 g_wqh[Dd*Dd],  g_wql[Dd*Dd];
__device__ bf16 g_wkh[Dd*Dd],  g_wkl[Dd*Dd];
__device__ bf16 g_wvh[Dd*Dd],  g_wvl[Dd*Dd];
__device__ bf16 g_woh[Dd*Dd],  g_wol[Dd*Dd];
__device__ bf16 g_w1h[Ff*Dd],  g_w1l[Ff*Dd];
__device__ bf16 g_w2h[Dd*Ff],  g_w2l[Dd*Ff];

// ------------------------------ helpers ------------------------------------
__device__ __forceinline__ uint32_t smem_u32(const void* p) {
    uint32_t a;
    asm("{ .reg .u64 t; cvta.to.shared.u64 t, %1; cvt.u32.u64 %0, t; }"
        : "=r"(a) : "l"(p));
    return a;
}
__device__ __forceinline__ void cp16(uint32_t s, const void* g) {
    asm volatile("cp.async.cg.shared.global [%0], [%1], 16;" :: "r"(s), "l"(g));
}
#define CP_COMMIT() asm volatile("cp.async.commit_group;" ::: "memory")
#define CP_WAIT0()  asm volatile("cp.async.wait_group 0;" ::: "memory")
#define CP_WAIT1()  asm volatile("cp.async.wait_group 1;" ::: "memory")

#define SWZ(x) ((x) ^ (((x) >> 3) & 0x70))

__device__ __forceinline__ void ldsm4(uint32_t* r, uint32_t a) {
    asm volatile("ldmatrix.sync.aligned.m8n8.x4.shared.b16 {%0,%1,%2,%3}, [%4];"
        : "=r"(r[0]), "=r"(r[1]), "=r"(r[2]), "=r"(r[3]) : "r"(a));
}
__device__ __forceinline__ void ldsm4t(uint32_t* r, uint32_t a) {
    asm volatile("ldmatrix.sync.aligned.m8n8.x4.trans.shared.b16 {%0,%1,%2,%3}, [%4];"
        : "=r"(r[0]), "=r"(r[1]), "=r"(r[2]), "=r"(r[3]) : "r"(a));
}
__device__ __forceinline__ void mma_bf16(float* d, const uint32_t* a, const uint32_t* b) {
    asm volatile(
        "mma.sync.aligned.m16n8k16.row.col.f32.bf16.bf16.f32 "
        "{%0,%1,%2,%3}, {%4,%5,%6,%7}, {%8,%9}, {%0,%1,%2,%3};"
        : "+f"(d[0]), "+f"(d[1]), "+f"(d[2]), "+f"(d[3])
        : "r"(a[0]), "r"(a[1]), "r"(a[2]), "r"(a[3]), "r"(b[0]), "r"(b[1]));
}
__device__ __forceinline__ uint32_t packbf(float a, float b) {
    __nv_bfloat162 t = __floats2bfloat162_rn(a, b);
    return reinterpret_cast<uint32_t&>(t);
}
__device__ __forceinline__ float gelu_exact(float v) {
    return 0.5f * v * (1.0f + erff(v * 0.70710678118654752440f));
}

// ----------------------------- GEMM (mma) ----------------------------------
// C[m,n] = sum_k (Ah+Al)[m,k]*(Wh+Wl)[n,k].  BM=128 BN=256 BK=64, 256 thr.
// 8 warps (2x4), warp tile 64x64: 4 m-atoms x 8 n-atoms of m16n8k16.

#define GSTG 98304                 // bytes per stage: A(h,l) 32K + B(h,l) 64K
#define GEMM_SMEM (2*GSTG)

#define EPI_HEADS 0
#define EPI_RES   1
#define EPI_GELU  2

template<int EPI>
__global__ void __launch_bounds__(256) gemm_mma(
    const bf16* __restrict__ A_h, const bf16* __restrict__ A_l,
    const bf16* __restrict__ W_h, const bf16* __restrict__ W_l,
    const float* __restrict__ bias, const float* __restrict__ res,
    float* __restrict__ Cf, bf16* __restrict__ Ch, bf16* __restrict__ Cl,
    int N, int K, float scale)
{
    extern __shared__ char smem[];
    const uint32_t sb = smem_u32(smem);
    const int tid = threadIdx.x;
    const int lane = tid & 31, wid = tid >> 5;
    const int wr = wid >> 2, wc = wid & 3;
    const int m0 = blockIdx.y * 128, n0 = blockIdx.x * 256;
    const int KT = K >> 6;

    float acc[4][8][4];
#pragma unroll
    for (int i = 0; i < 4; i++)
#pragma unroll
        for (int j = 0; j < 8; j++)
#pragma unroll
            for (int e = 0; e < 4; e++) acc[i][j][e] = 0.f;

    // stage loader
    auto load_stage = [&](int st, int kt) {
        const uint32_t s0 = sb + st * GSTG;
        const int k0 = kt * 64;
#pragma unroll
        for (int t = 0; t < 4; t++) {
            int idx = t * 256 + tid;
            int row = idx >> 3, c = idx & 7;
            uint32_t off = SWZ((uint32_t)(row * 128 + c * 16));
            size_t go = (size_t)(m0 + row) * K + k0 + c * 8;
            cp16(s0 + off,         A_h + go);
            cp16(s0 + 16384 + off, A_l + go);
        }
#pragma unroll
        for (int t = 0; t < 8; t++) {
            int idx = t * 256 + tid;
            int row = idx >> 3, c = idx & 7;
            uint32_t off = SWZ((uint32_t)(row * 128 + c * 16));
            size_t go = (size_t)(n0 + row) * K + k0 + c * 8;
            cp16(s0 + 32768 + off, W_h + go);
            cp16(s0 + 65536 + off, W_l + go);
        }
    };

    load_stage(0, 0);
    CP_COMMIT();

    const int lr16 = lane & 15;
    const int alc  = (lane >> 4) * 16;
    const int brow = wc * 64 + (lane & 7) + ((lane >> 4) & 1) * 8;
    const int bcol = ((lane >> 3) & 1) * 16;

    for (int kt = 0; kt < KT; kt++) {
        if (kt + 1 < KT) { load_stage((kt + 1) & 1, kt + 1); CP_COMMIT(); CP_WAIT1(); }
        else             { CP_WAIT0(); }
        __syncthreads();

        const uint32_t sA  = sb + (kt & 1) * GSTG;
        const uint32_t sAl = sA + 16384;
        const uint32_t sB  = sA + 32768;
        const uint32_t sBl = sA + 65536;

#pragma unroll
        for (int ks = 0; ks < 4; ks++) {
            uint32_t ah[4][4], al[4][4];
#pragma unroll
            for (int i = 0; i < 4; i++) {
                uint32_t off = SWZ((uint32_t)((wr * 64 + i * 16 + lr16) * 128 + ks * 32 + alc));
                ldsm4(ah[i], sA  + off);
                ldsm4(al[i], sAl + off);
            }
#pragma unroll
            for (int p = 0; p < 4; p++) {
                uint32_t boff = SWZ((uint32_t)((brow + p * 16) * 128 + ks * 32 + bcol));
                uint32_t bh[4], bl[4];
                ldsm4(bh, sB  + boff);
                ldsm4(bl, sBl + boff);
#pragma unroll
                for (int a = 0; a < 2; a++) {
#pragma unroll
                    for (int i = 0; i < 4; i++) {
                        mma_bf16(acc[i][p * 2 + a], ah[i], &bh[2 * a]);
                        mma_bf16(acc[i][p * 2 + a], ah[i], &bl[2 * a]);
                        mma_bf16(acc[i][p * 2 + a], al[i], &bh[2 * a]);
                    }
                }
            }
        }
        __syncthreads();
    }

    // epilogue
#pragma unroll
    for (int i = 0; i < 4; i++) {
        const int r0 = m0 + wr * 64 + i * 16 + (lane >> 2);
#pragma unroll
        for (int j = 0; j < 8; j++) {
            const int n = n0 + wc * 64 + j * 8 + 2 * (lane & 3);
            const float2 b2 = *(const float2*)&bias[n];
#pragma unroll
            for (int hf = 0; hf < 2; hf++) {
                const int m = r0 + hf * 8;
                float v0 = acc[i][j][hf * 2 + 0] + b2.x;
                float v1 = acc[i][j][hf * 2 + 1] + b2.y;
                if (EPI == EPI_HEADS) {
                    v0 *= scale; v1 *= scale;
                    const size_t o = (((size_t)(m >> 10) * Hh + (n >> 6)) * Ss + (m & 1023)) * DH + (n & 63);
                    const float h0 = __bfloat162float(__float2bfloat16(v0));
                    const float h1 = __bfloat162float(__float2bfloat16(v1));
                    *(uint32_t*)(Ch + o) = packbf(h0, h1);
                    *(uint32_t*)(Cl + o) = packbf(v0 - h0, v1 - h1);
                } else if (EPI == EPI_RES) {
                    const size_t o = (size_t)m * N + n;
                    const float2 rr = *(const float2*)&res[o];
                    float2 w; w.x = v0 + rr.x; w.y = v1 + rr.y;
                    *(float2*)&Cf[o] = w;
                } else { // EPI_GELU -> bf16 hi/lo
                    const size_t o = (size_t)m * N + n;
                    const float g0 = gelu_exact(v0), g1 = gelu_exact(v1);
                    const float h0 = __bfloat162float(__float2bfloat16(g0));
                    const float h1 = __bfloat162float(__float2bfloat16(g1));
                    *(uint32_t*)(Ch + o) = packbf(h0, h1);
                    *(uint32_t*)(Cl + o) = packbf(g0 - h0, g1 - h1);
                }
            }
        }
    }
}

// --------------------------- flash attention (mma) --------------------------
// Block = (b,h,128 q-rows). 8 warps, warp = 16 rows. KV tiles of 128, 2 stages.
// smem: Qh 16K, Ql 16K | stage: Kh,Kl,Vh,Vl 16K each | mask 2x512B.
#define ATT_Q   0
#define ATT_ST  32768
#define ATT_STG 65536
#define ATT_MSK (ATT_ST + 2*ATT_STG)
#define ATT_SMEM (ATT_MSK + 1024)

__global__ void __launch_bounds__(256) attn_mma(
    const bf16* __restrict__ qh, const bf16* __restrict__ ql,
    const bf16* __restrict__ kh, const bf16* __restrict__ kl,
    const bf16* __restrict__ vh, const bf16* __restrict__ vl,
    const float* __restrict__ mf,
    bf16* __restrict__ oh, bf16* __restrict__ ol)
{
    extern __shared__ char smem[];
    const uint32_t sb = smem_u32(smem);
    const int tid = threadIdx.x;
    const int lane = tid & 31, wid = tid >> 5;
    const int b = blockIdx.z, h = blockIdx.y, q0 = blockIdx.x * 128;

    const size_t bh_off = ((size_t)(b * Hh + h) * Ss) * DH;
    const bf16* qhp = qh + bh_off + (size_t)q0 * DH;
    const bf16* qlp = ql + bh_off + (size_t)q0 * DH;
    const bf16* khp = kh + bh_off;
    const bf16* klp = kl + bh_off;
    const bf16* vhp = vh + bh_off;
    const bf16* vlp = vl + bh_off;
    const float* mfb = mf + b * Ss;

    auto load_kv = [&](int st, int kt) {
        const uint32_t s0 = sb + ATT_ST + st * ATT_STG;
        const int kv0 = kt * 128;
#pragma unroll
        for (int t = 0; t < 4; t++) {
            int idx = t * 256 + tid;
            int row = idx >> 3, c = idx & 7;
            uint32_t off = SWZ((uint32_t)(row * 128 + c * 16));
            size_t go = (size_t)(kv0 + row) * DH + c * 8;
            cp16(s0 + off,         khp + go);
            cp16(s0 + 16384 + off, klp + go);
            cp16(s0 + 32768 + off, vhp + go);
            cp16(s0 + 49152 + off, vlp + go);
        }
        if (tid < 32) cp16(sb + ATT_MSK + st * 512 + tid * 16, mfb + kv0 + tid * 4);
    };

    // prologue: Q + kv0
    {
#pragma unroll
        for (int t = 0; t < 4; t++) {
            int idx = t * 256 + tid;
            int row = idx >> 3, c = idx & 7;
            uint32_t off = SWZ((uint32_t)(row * 128 + c * 16));
            size_t go = (size_t)row * DH + c * 8;
            cp16(sb + ATT_Q + off,         qhp + go);
            cp16(sb + ATT_Q + 16384 + off, qlp + go);
        }
        load_kv(0, 0);
        CP_COMMIT();
    }

    uint32_t qfh[4][4], qfl[4][4];
    float oacc[8][4];
#pragma unroll
    for (int q = 0; q < 8; q++)
#pragma unroll
        for (int e = 0; e < 4; e++) oacc[q][e] = 0.f;
    float mrow0 = -INFINITY, mrow1 = -INFINITY, lsum0 = 0.f, lsum1 = 0.f;

    const int lr16 = lane & 15;
    const int alc  = (lane >> 4) * 16;
    const int brow = (lane & 7) + ((lane >> 4) & 1) * 8;
    const int bcol = ((lane >> 3) & 1) * 16;
    const int vrow = (lane & 7) + ((lane >> 3) & 1) * 8;
    const int vcol = (lane >> 4) * 16;

    const int NKV = Ss / 128;
    for (int kt = 0; kt < NKV; kt++) {
        if (kt + 1 < NKV) { load_kv((kt + 1) & 1, kt + 1); CP_COMMIT(); CP_WAIT1(); }
        else              { CP_WAIT0(); }
        __syncthreads();

        if (kt == 0) {
#pragma unroll
            for (int ks = 0; ks < 4; ks++) {
                uint32_t off = SWZ((uint32_t)((wid * 16 + lr16) * 128 + ks * 32 + alc));
                ldsm4(qfh[ks], sb + ATT_Q + off);
                ldsm4(qfl[ks], sb + ATT_Q + 16384 + off);
            }
        }

        const uint32_t sK  = sb + ATT_ST + (kt & 1) * ATT_STG;
        const uint32_t sKl = sK + 16384;
        const uint32_t sV  = sK + 32768;
        const uint32_t sVl = sK + 49152;
        const uint32_t sM  = sb + ATT_MSK + (kt & 1) * 512;

        // ---- S = Q K^T ----
        float sacc[16][4];
#pragma unroll
        for (int j = 0; j < 16; j++)
#pragma unroll
            for (int e = 0; e < 4; e++) sacc[j][e] = 0.f;

#pragma unroll
        for (int p = 0; p < 8; p++) {
#pragma unroll
            for (int ks = 0; ks < 4; ks++) {
                uint32_t koff = SWZ((uint32_t)((p * 16 + brow) * 128 + ks * 32 + bcol));
                uint32_t kbh[4], kbl[4];
                ldsm4(kbh, sK  + koff);
                ldsm4(kbl, sKl + koff);
#pragma unroll
                for (int a = 0; a < 2; a++) {
                    mma_bf16(sacc[p * 2 + a], qfh[ks], &kbh[2 * a]);
                    mma_bf16(sacc[p * 2 + a], qfh[ks], &kbl[2 * a]);
                    mma_bf16(sacc[p * 2 + a], qfl[ks], &kbh[2 * a]);
                }
            }
        }

        // ---- softmax (online) ----
        float mx0 = -INFINITY, mx1 = -INFINITY;
#pragma unroll
        for (int j = 0; j < 16; j++) {
            mx0 = fmaxf(mx0, fmaxf(sacc[j][0], sacc[j][1]));
            mx1 = fmaxf(mx1, fmaxf(sacc[j][2], sacc[j][3]));
        }
        mx0 = fmaxf(mx0, __shfl_xor_sync(0xffffffffu, mx0, 1));
        mx0 = fmaxf(mx0, __shfl_xor_sync(0xffffffffu, mx0, 2));
        mx1 = fmaxf(mx1, __shfl_xor_sync(0xffffffffu, mx1, 1));
        mx1 = fmaxf(mx1, __shfl_xor_sync(0xffffffffu, mx1, 2));
        const float mnew0 = fmaxf(mrow0, mx0);
        const float mnew1 = fmaxf(mrow1, mx1);
        const float al0 = __expf(mrow0 - mnew0);
        const float al1 = __expf(mrow1 - mnew1);
        float ls0 = 0.f, ls1 = 0.f;
#pragma unroll
        for (int j = 0; j < 16; j++) {
            float2 mv;
            asm volatile("ld.shared.v2.f32 {%0,%1}, [%2];"
                : "=f"(mv.x), "=f"(mv.y)
                : "r"(sM + (uint32_t)((j * 8 + 2 * (lane & 3)) * 4)));
            float p0 = __expf(sacc[j][0] - mnew0) * mv.x;
            float p1 = __expf(sacc[j][1] - mnew0) * mv.y;
            float p2 = __expf(sacc[j][2] - mnew1) * mv.x;
            float p3 = __expf(sacc[j][3] - mnew1) * mv.y;
            sacc[j][0] = p0; sacc[j][1] = p1; sacc[j][2] = p2; sacc[j][3] = p3;
            ls0 += p0 + p1; ls1 += p2 + p3;
        }
        ls0 += __shfl_xor_sync(0xffffffffu, ls0, 1);
        ls0 += __shfl_xor_sync(0xffffffffu, ls0, 2);
        ls1 += __shfl_xor_sync(0xffffffffu, ls1, 1);
        ls1 += __shfl_xor_sync(0xffffffffu, ls1, 2);
        lsum0 = lsum0 * al0 + ls0;
        lsum1 = lsum1 * al1 + ls1;
        mrow0 = mnew0; mrow1 = mnew1;
#pragma unroll
        for (int q = 0; q < 8; q++) {
            oacc[q][0] *= al0; oacc[q][1] *= al0;
            oacc[q][2] *= al1; oacc[q][3] *= al1;
        }

        // ---- O += P V ----
#pragma unroll
        for (int ks = 0; ks < 8; ks++) {
            uint32_t ph[4], pl[4];
            {
                const float* s0 = sacc[2 * ks];
                const float* s1 = sacc[2 * ks + 1];
                float h00 = __bfloat162float(__float2bfloat16(s0[0]));
                float h01 = __bfloat162float(__float2bfloat16(s0[1]));
                float h02 = __bfloat162float(__float2bfloat16(s0[2]));
                float h03 = __bfloat162float(__float2bfloat16(s0[3]));
                float h10 = __bfloat162float(__float2bfloat16(s1[0]));
                float h11 = __bfloat162float(__float2bfloat16(s1[1]));
                float h12 = __bfloat162float(__float2bfloat16(s1[2]));
                float h13 = __bfloat162float(__float2bfloat16(s1[3]));
                ph[0] = packbf(h00, h01); ph[1] = packbf(h02, h03);
                ph[2] = packbf(h10, h11); ph[3] = packbf(h12, h13);
                pl[0] = packbf(s0[0] - h00, s0[1] - h01);
                pl[1] = packbf(s0[2] - h02, s0[3] - h03);
                pl[2] = packbf(s1[0] - h10, s1[1] - h11);
                pl[3] = packbf(s1[2] - h12, s1[3] - h13);
            }
#pragma unroll
            for (int q = 0; q < 4; q++) {
                uint32_t voff = SWZ((uint32_t)((ks * 16 + vrow) * 128 + q * 32 + vcol));
                uint32_t vbh[4], vbl[4];
                ldsm4t(vbh, sV  + voff);
                ldsm4t(vbl, sVl + voff);
#pragma unroll
                for (int a = 0; a < 2; a++) {
                    mma_bf16(oacc[q * 2 + a], ph, &vbh[2 * a]);
                    mma_bf16(oacc[q * 2 + a], ph, &vbl[2 * a]);
                    mma_bf16(oacc[q * 2 + a], pl, &vbh[2 * a]);
                }
            }
        }
        __syncthreads();
    }

    // ---- write ctx (bf16 hi/lo, [token][d]) ----
    const float inv0 = 1.f / lsum0;
    const float inv1 = 1.f / lsum1;
    const int tok0 = b * Ss + q0 + wid * 16 + (lane >> 2);
#pragma unroll
    for (int q = 0; q < 8; q++) {
        const int col = h * DH + q * 8 + 2 * (lane & 3);
        {
            float v0 = oacc[q][0] * inv0, v1 = oacc[q][1] * inv0;
            const size_t o = (size_t)tok0 * Dd + col;
            float h0 = __bfloat162float(__float2bfloat16(v0));
            float h1 = __bfloat162float(__float2bfloat16(v1));
            *(uint32_t*)(oh + o) = packbf(h0, h1);
            *(uint32_t*)(ol + o) = packbf(v0 - h0, v1 - h1);
        }
        {
            float v0 = oacc[q][2] * inv1, v1 = oacc[q][3] * inv1;
            const size_t o = (size_t)(tok0 + 8) * Dd + col;
            float h0 = __bfloat162float(__float2bfloat16(v0));
            float h1 = __bfloat162float(__float2bfloat16(v1));
            *(uint32_t*)(oh + o) = packbf(h0, h1);
            *(uint32_t*)(ol + o) = packbf(v0 - h0, v1 - h1);
        }
    }
}

// ------------------------------ LayerNorm -----------------------------------
template<bool WB>
__global__ void __launch_bounds__(256) ln_k(
    const float* __restrict__ X, const float* __restrict__ gg,
    const float* __restrict__ bb, float* __restrict__ Y,
    bf16* __restrict__ Yh, bf16* __restrict__ Yl)
{
    __shared__ float red[16];
    const int row = blockIdx.x, tid = threadIdx.x;
    const float4 x = ((const float4*)(X + (size_t)row * Dd))[tid];
    float s  = x.x + x.y + x.z + x.w;
    float s2 = x.x*x.x + x.y*x.y + x.z*x.z + x.w*x.w;
#pragma unroll
    for (int o = 16; o; o >>= 1) {
        s  += __shfl_xor_sync(0xffffffffu, s,  o);
        s2 += __shfl_xor_sync(0xffffffffu, s2, o);
    }
    const int w = tid >> 5, lane = tid & 31;
    if (lane == 0) { red[w] = s; red[8 + w] = s2; }
    __syncthreads();
    if (tid < 32) {
        float a = (tid < 8) ? red[tid]     : 0.f;
        float c = (tid < 8) ? red[8 + tid] : 0.f;
#pragma unroll
        for (int o = 4; o; o >>= 1) {
            a += __shfl_xor_sync(0xffffffffu, a, o);
            c += __shfl_xor_sync(0xffffffffu, c, o);
        }
        if (tid == 0) { red[0] = a; red[8] = c; }
    }
    __syncthreads();
    const float mean = red[0] * (1.f / Dd);
    const float var  = red[8] * (1.f / Dd) - mean * mean;
    const float rstd = rsqrtf(var + 1e-12f);
    const float4 gv = ((const float4*)gg)[tid];
    const float4 bv = ((const float4*)bb)[tid];
    float4 y;
    y.x = (x.x - mean) * rstd * gv.x + bv.x;
    y.y = (x.y - mean) * rstd * gv.y + bv.y;
    y.z = (x.z - mean) * rstd * gv.z + bv.z;
    y.w = (x.w - mean) * rstd * gv.w + bv.w;
    ((float4*)(Y + (size_t)row * Dd))[tid] = y;
    if (WB) {
        float h0 = __bfloat162float(__float2bfloat16(y.x));
        float h1 = __bfloat162float(__float2bfloat16(y.y));
        float h2 = __bfloat162float(__float2bfloat16(y.z));
        float h3 = __bfloat162float(__float2bfloat16(y.w));
        uint32_t* yh = (uint32_t*)(Yh + (size_t)row * Dd);
        uint32_t* yl = (uint32_t*)(Yl + (size_t)row * Dd);
        yh[tid*2]   = packbf(h0, h1);
        yh[tid*2+1] = packbf(h2, h3);
        yl[tid*2]   = packbf(y.x - h0, y.y - h1);
        yl[tid*2+1] = packbf(y.z - h2, y.w - h3);
    }
}

// -------------------------- fp32 -> bf16 hi/lo ------------------------------
__global__ void __launch_bounds__(256) cvt_k(
    const float* __restrict__ X, bf16* __restrict__ Hc,
    bf16* __restrict__ Lc, int n4)
{
    int i = blockIdx.x * 256 + threadIdx.x;
    if (i >= n4) return;
    float4 v = ((const float4*)X)[i];
    float h0 = __bfloat162float(__float2bfloat16(v.x));
    float h1 = __bfloat162float(__float2bfloat16(v.y));
    float h2 = __bfloat162float(__float2bfloat16(v.z));
    float h3 = __bfloat162float(__float2bfloat16(v.w));
    ((uint32_t*)Hc)[i*2]   = packbf(h0, h1);
    ((uint32_t*)Hc)[i*2+1] = packbf(h2, h3);
    ((uint32_t*)Lc)[i*2]   = packbf(v.x - h0, v.y - h1);
    ((uint32_t*)Lc)[i*2+1] = packbf(v.z - h2, v.w - h3);
}

__global__ void __launch_bounds__(256) maskf_k(const int* __restrict__ m,
                                              float* __restrict__ mfo, int n)
{
    int i = blockIdx.x * 256 + threadIdx.x;
    if (i < n) mfo[i] = (m[i] != 0) ? 1.f : 0.f;
}

// ------------------------------ launch --------------------------------------
extern "C" void kernel_launch(void* const* d_in, const int* in_sizes, int n_in,
                              void* d_out, int out_size)
{
    const float* x    = (const float*)d_in[0];
    const int*   amsk = (const int*)  d_in[1];
    const float* Wq   = (const float*)d_in[2];
    const float* bq   = (const float*)d_in[3];
    const float* Wk   = (const float*)d_in[4];
    const float* bk   = (const float*)d_in[5];
    const float* Wv   = (const float*)d_in[6];
    const float* bv   = (const float*)d_in[7];
    const float* Wo   = (const float*)d_in[8];
    const float* bo   = (const float*)d_in[9];
    const float* ln1g = (const float*)d_in[10];
    const float* ln1b = (const float*)d_in[11];
    const float* W1   = (const float*)d_in[12];
    const float* b1   = (const float*)d_in[13];
    const float* W2   = (const float*)d_in[14];
    const float* b2   = (const float*)d_in[15];
    const float* ln2g = (const float*)d_in[16];
    const float* ln2b = (const float*)d_in[17];
    float* out = (float*)d_out;

    float *sap, *hp, *f2p, *mfp;
    bf16 *xh, *xl, *qhp, *qlp, *khp, *klp, *vhp, *vlp, *cxh, *cxl;
    bf16 *hhp, *hlp, *fhp, *flp;
    bf16 *wqh, *wql, *wkh, *wkl, *wvh, *wvl, *woh, *wol, *w1h, *w1l, *w2h, *w2l;
    cudaGetSymbolAddress((void**)&sap, g_sa);  cudaGetSymbolAddress((void**)&hp,  g_h);
    cudaGetSymbolAddress((void**)&f2p, g_f2);  cudaGetSymbolAddress((void**)&mfp, g_mf);
    cudaGetSymbolAddress((void**)&xh,  g_xh);  cudaGetSymbolAddress((void**)&xl,  g_xl);
    cudaGetSymbolAddress((void**)&qhp, g_qh);  cudaGetSymbolAddress((void**)&qlp, g_ql);
    cudaGetSymbolAddress((void**)&khp, g_kh);  cudaGetSymbolAddress((void**)&klp, g_kl);
    cudaGetSymbolAddress((void**)&vhp, g_vh);  cudaGetSymbolAddress((void**)&vlp, g_vl);
    cudaGetSymbolAddress((void**)&cxh, g_cxh); cudaGetSymbolAddress((void**)&cxl, g_cxl);
    cudaGetSymbolAddress((void**)&hhp, g_hh);  cudaGetSymbolAddress((void**)&hlp, g_hl);
    cudaGetSymbolAddress((void**)&fhp, g_fh);  cudaGetSymbolAddress((void**)&flp, g_fl);
    cudaGetSymbolAddress((void**)&wqh, g_wqh); cudaGetSymbolAddress((void**)&wql, g_wql);
    cudaGetSymbolAddress((void**)&wkh, g_wkh); cudaGetSymbolAddress((void**)&wkl, g_wkl);
    cudaGetSymbolAddress((void**)&wvh, g_wvh); cudaGetSymbolAddress((void**)&wvl, g_wvl);
    cudaGetSymbolAddress((void**)&woh, g_woh); cudaGetSymbolAddress((void**)&wol, g_wol);
    cudaGetSymbolAddress((void**)&w1h, g_w1h); cudaGetSymbolAddress((void**)&w1l, g_w1l);
    cudaGetSymbolAddress((void**)&w2h, g_w2h); cudaGetSymbolAddress((void**)&w2l, g_w2l);

    cudaFuncSetAttribute(gemm_mma<EPI_HEADS>, cudaFuncAttributeMaxDynamicSharedMemorySize, GEMM_SMEM);
    cudaFuncSetAttribute(gemm_mma<EPI_RES>,   cudaFuncAttributeMaxDynamicSharedMemorySize, GEMM_SMEM);
    cudaFuncSetAttribute(gemm_mma<EPI_GELU>,  cudaFuncAttributeMaxDynamicSharedMemorySize, GEMM_SMEM);
    cudaFuncSetAttribute(attn_mma, cudaFuncAttributeMaxDynamicSharedMemorySize, ATT_SMEM);

    // 0. conversions
    cvt_k<<<(TT*Dd/4 + 255)/256, 256>>>(x,  xh,  xl,  TT*Dd/4);
    cvt_k<<<(Dd*Dd/4 + 255)/256, 256>>>(Wq, wqh, wql, Dd*Dd/4);
    cvt_k<<<(Dd*Dd/4 + 255)/256, 256>>>(Wk, wkh, wkl, Dd*Dd/4);
    cvt_k<<<(Dd*Dd/4 + 255)/256, 256>>>(Wv, wvh, wvl, Dd*Dd/4);
    cvt_k<<<(Dd*Dd/4 + 255)/256, 256>>>(Wo, woh, wol, Dd*Dd/4);
    cvt_k<<<(Ff*Dd/4 + 255)/256, 256>>>(W1, w1h, w1l, Ff*Dd/4);
    cvt_k<<<(Dd*Ff/4 + 255)/256, 256>>>(W2, w2h, w2l, Dd*Ff/4);
    maskf_k<<<(Bb*Ss + 255)/256, 256>>>(amsk, mfp, Bb*Ss);

    dim3 gD(Dd/256, TT/128);    // (4, 64)
    dim3 gF(Ff/256, TT/128);    // (16, 64)

    // 1-3. QKV projections -> bf16 hi/lo heads layout
    gemm_mma<EPI_HEADS><<<gD, 256, GEMM_SMEM>>>(xh, xl, wqh, wql, bq, nullptr,
                                                nullptr, qhp, qlp, Dd, Dd, 0.125f);
    gemm_mma<EPI_HEADS><<<gD, 256, GEMM_SMEM>>>(xh, xl, wkh, wkl, bk, nullptr,
                                                nullptr, khp, klp, Dd, Dd, 1.0f);
    gemm_mma<EPI_HEADS><<<gD, 256, GEMM_SMEM>>>(xh, xl, wvh, wvl, bv, nullptr,
                                                nullptr, vhp, vlp, Dd, Dd, 1.0f);

    // 4. attention -> ctx bf16 hi/lo
    attn_mma<<<dim3(Ss/128, Hh, Bb), 256, ATT_SMEM>>>(qhp, qlp, khp, klp, vhp, vlp,
                                                      mfp, cxh, cxl);

    // 5. output projection + residual (fp32)
    gemm_mma<EPI_RES><<<gD, 256, GEMM_SMEM>>>(cxh, cxl, woh, wol, bo, x,
                                              sap, nullptr, nullptr, Dd, Dd, 1.0f);

    // 6. LN1 -> fp32 + bf16 hi/lo
    ln_k<true><<<TT, 256>>>(sap, ln1g, ln1b, hp, hhp, hlp);

    // 7. FFN up + gelu -> bf16 hi/lo
    gemm_mma<EPI_GELU><<<gF, 256, GEMM_SMEM>>>(hhp, hlp, w1h, w1l, b1, nullptr,
                                               nullptr, fhp, flp, Ff, Dd, 1.0f);

    // 8. FFN down + residual (fp32)
    gemm_mma<EPI_RES><<<gD, 256, GEMM_SMEM>>>(fhp, flp, w2h, w2l, b2, hp,
                                              f2p, nullptr, nullptr, Dd, Ff, 1.0f);

    // 9. LN2 -> output
    ln_k<false><<<TT, 256>>>(f2p, ln2g, ln2b, out, nullptr, nullptr);
}